// round 4
// baseline (speedup 1.0000x reference)
#include <cuda_runtime.h>

#define N_NODES  100000
#define N_EDGES  1600000
#define N_GRAPHS 1000
#define D        64
#define NB_SCAN  ((N_NODES + 255) / 256)   // 391

// ---------------- device scratch (no allocations allowed) ----------------
__device__ int   g_deg[N_NODES];
__device__ int   g_off[N_NODES];           // CSR row offsets
__device__ int   g_cursor[N_NODES];        // fill cursors
__device__ int   g_bsum[NB_SCAN];
__device__ int   g_boff[NB_SCAN];
__device__ int   g_csr[N_EDGES];           // src indices grouped by dst
__device__ float g_dinv[N_NODES];
__device__ float g_h[(size_t)N_NODES * D];    // GEMM output (unscaled)
__device__ float g_agg[(size_t)N_NODES * D];  // aggregation output

// ---------------- degree / norm ----------------
__global__ void k_deg_init() {
    int i = blockIdx.x * blockDim.x + threadIdx.x;
    if (i < N_NODES) g_deg[i] = 1;  // self-loop
}

__global__ void k_deg_count(const int* __restrict__ ei) {
    int e = blockIdx.x * blockDim.x + threadIdx.x;
    if (e < N_EDGES) atomicAdd(&g_deg[ei[N_EDGES + e]], 1);  // dst row
}

__global__ void k_dinv() {
    int i = blockIdx.x * blockDim.x + threadIdx.x;
    if (i < N_NODES) {
        g_dinv[i] = rsqrtf((float)g_deg[i]);
        g_cursor[i] = 0;
    }
}

// ---------------- 3-pass exclusive scan of (deg-1) into g_off ----------------
__global__ __launch_bounds__(256) void k_scanA() {
    __shared__ int s[256];
    int tid = threadIdx.x;
    int i = blockIdx.x * 256 + tid;
    int v = (i < N_NODES) ? (g_deg[i] - 1) : 0;
    s[tid] = v;
    __syncthreads();
#pragma unroll
    for (int o = 1; o < 256; o <<= 1) {
        int t = (tid >= o) ? s[tid - o] : 0;
        __syncthreads();
        s[tid] += t;
        __syncthreads();
    }
    if (i < N_NODES) g_off[i] = s[tid] - v;          // exclusive
    if (tid == 255) g_bsum[blockIdx.x] = s[255];
}

__global__ __launch_bounds__(512) void k_scanB() {
    __shared__ int s[512];
    int tid = threadIdx.x;
    int v = (tid < NB_SCAN) ? g_bsum[tid] : 0;
    s[tid] = v;
    __syncthreads();
#pragma unroll
    for (int o = 1; o < 512; o <<= 1) {
        int t = (tid >= o) ? s[tid - o] : 0;
        __syncthreads();
        s[tid] += t;
        __syncthreads();
    }
    if (tid < NB_SCAN) g_boff[tid] = s[tid] - v;     // exclusive
}

__global__ __launch_bounds__(256) void k_scanC() {
    int i = blockIdx.x * 256 + threadIdx.x;
    if (i < N_NODES) g_off[i] += g_boff[i >> 8];
}

// ---------------- CSR fill: group src indices by dst ----------------
__global__ __launch_bounds__(256) void k_fill(const int* __restrict__ ei) {
    int e = blockIdx.x * blockDim.x + threadIdx.x;
    if (e < N_EDGES) {
        int src = ei[e];
        int dst = ei[N_EDGES + e];
        int pos = g_off[dst] + atomicAdd(&g_cursor[dst], 1);
        g_csr[pos] = src;
    }
}

// ---------------- GEMM: h = act(in)[N,64] @ W[64,64]  (no epilogue scaling) ----------------
template<bool RELU_IN>
__global__ __launch_bounds__(128) void k_gcn_gemm(const float* __restrict__ in,
                                                  const float* __restrict__ W,
                                                  float* __restrict__ h) {
    __shared__ float Xt[64][128];   // [k][swizzled row]   32KB
    __shared__ float Ws[64][64];    // [k][col]            16KB

    const int tid = threadIdx.x;        // 0..127
    const int rowBase = blockIdx.x * 128;

    // ---- stage W ----
    {
        const float4* W4 = (const float4*)W;
        float4* Ws4 = (float4*)Ws;
#pragma unroll
        for (int i = 0; i < 8; i++) Ws4[tid + i * 128] = W4[tid + i * 128];
    }

    // ---- stage X transposed ----
#pragma unroll
    for (int i = 0; i < 16; i++) {
        int f4  = tid + i * 128;        // 0..2047
        int r   = f4 >> 4;
        int c4  = f4 & 15;
        int row = rowBase + r;
        float4 v = make_float4(0.f, 0.f, 0.f, 0.f);
        if (row < N_NODES) v = ((const float4*)in)[(size_t)row * 16 + c4];
        if (RELU_IN) {
            v.x = fmaxf(v.x, 0.f); v.y = fmaxf(v.y, 0.f);
            v.z = fmaxf(v.z, 0.f); v.w = fmaxf(v.w, 0.f);
        }
        int rsw = (((r >> 3) ^ c4) << 3) | (r & 7);
        Xt[c4 * 4 + 0][rsw] = v.x;
        Xt[c4 * 4 + 1][rsw] = v.y;
        Xt[c4 * 4 + 2][rsw] = v.z;
        Xt[c4 * 4 + 3][rsw] = v.w;
    }
    __syncthreads();

    const int rg  = tid >> 3;
    const int cg8 = (tid & 7) * 8;

    float acc[8][8];
#pragma unroll
    for (int i = 0; i < 8; i++)
#pragma unroll
        for (int j = 0; j < 8; j++) acc[i][j] = 0.f;

#pragma unroll 8
    for (int k = 0; k < 64; k++) {
        int rgx = ((rg ^ (k >> 2)) << 3);
        float4 xa = *(const float4*)&Xt[k][rgx];
        float4 xb = *(const float4*)&Xt[k][rgx + 4];
        float4 wa = *(const float4*)&Ws[k][cg8];
        float4 wb = *(const float4*)&Ws[k][cg8 + 4];
        float xv[8] = {xa.x, xa.y, xa.z, xa.w, xb.x, xb.y, xb.z, xb.w};
        float wv[8] = {wa.x, wa.y, wa.z, wa.w, wb.x, wb.y, wb.z, wb.w};
#pragma unroll
        for (int i = 0; i < 8; i++)
#pragma unroll
            for (int j = 0; j < 8; j++)
                acc[i][j] += xv[i] * wv[j];
    }

#pragma unroll
    for (int i = 0; i < 8; i++) {
        int row = rowBase + rg * 8 + i;
        if (row >= N_NODES) break;
        size_t o = (size_t)row * 16 + (cg8 >> 2);
        ((float4*)h)[o + 0] = make_float4(acc[i][0], acc[i][1], acc[i][2], acc[i][3]);
        ((float4*)h)[o + 1] = make_float4(acc[i][4], acc[i][5], acc[i][6], acc[i][7]);
    }
}

// ---------------- CSR gather (write-only output) ----------------
// agg[n] = dinv[n]^2 * h[n] + b + dinv[n] * sum_{s in csr[n]} dinv[s] * h[s]
__global__ __launch_bounds__(256) void k_gather(const float* __restrict__ h,
                                                const float* __restrict__ bias,
                                                float* __restrict__ agg) {
    int t = blockIdx.x * blockDim.x + threadIdx.x;
    int node = t >> 4;
    int lane = t & 15;
    if (node >= N_NODES) return;

    int start = g_off[node];
    int cnt   = g_deg[node] - 1;

    float4 a0 = make_float4(0.f, 0.f, 0.f, 0.f);
    float4 a1 = make_float4(0.f, 0.f, 0.f, 0.f);

    int i = 0;
    for (; i + 4 <= cnt; i += 4) {
        int s0 = g_csr[start + i + 0];
        int s1 = g_csr[start + i + 1];
        int s2 = g_csr[start + i + 2];
        int s3 = g_csr[start + i + 3];
        float d0 = g_dinv[s0], d1 = g_dinv[s1], d2 = g_dinv[s2], d3 = g_dinv[s3];
        float4 v0 = ((const float4*)h)[(size_t)s0 * 16 + lane];
        float4 v1 = ((const float4*)h)[(size_t)s1 * 16 + lane];
        float4 v2 = ((const float4*)h)[(size_t)s2 * 16 + lane];
        float4 v3 = ((const float4*)h)[(size_t)s3 * 16 + lane];
        a0.x += d0 * v0.x; a0.y += d0 * v0.y; a0.z += d0 * v0.z; a0.w += d0 * v0.w;
        a1.x += d1 * v1.x; a1.y += d1 * v1.y; a1.z += d1 * v1.z; a1.w += d1 * v1.w;
        a0.x += d2 * v2.x; a0.y += d2 * v2.y; a0.z += d2 * v2.z; a0.w += d2 * v2.w;
        a1.x += d3 * v3.x; a1.y += d3 * v3.y; a1.z += d3 * v3.z; a1.w += d3 * v3.w;
    }
    for (; i < cnt; i++) {
        int s0 = g_csr[start + i];
        float d0 = g_dinv[s0];
        float4 v0 = ((const float4*)h)[(size_t)s0 * 16 + lane];
        a0.x += d0 * v0.x; a0.y += d0 * v0.y; a0.z += d0 * v0.z; a0.w += d0 * v0.w;
    }

    float dv = g_dinv[node];
    float4 hv = ((const float4*)h)[(size_t)node * 16 + lane];
    float4 bv = ((const float4*)bias)[lane];
    float dv2 = dv * dv;
    float4 o;
    o.x = dv2 * hv.x + bv.x + dv * (a0.x + a1.x);
    o.y = dv2 * hv.y + bv.y + dv * (a0.y + a1.y);
    o.z = dv2 * hv.z + bv.z + dv * (a0.z + a1.z);
    o.w = dv2 * hv.w + bv.w + dv * (a0.w + a1.w);
    ((float4*)agg)[(size_t)node * 16 + lane] = o;
}

// ---------------- fused mean-pool (batch is sorted) + MLP head ----------------
__global__ __launch_bounds__(64) void k_pool_head(const float* __restrict__ agg,
                                                  const int* __restrict__ batch,
                                                  const float* __restrict__ lw1,
                                                  const float* __restrict__ lb1,
                                                  const float* __restrict__ lw2,
                                                  const float* __restrict__ lb2,
                                                  float* __restrict__ out) {
    int g = blockIdx.x;
    int tid = threadIdx.x;  // 64

    int l = 0, r = N_NODES;
    while (l < r) { int m = (l + r) >> 1; if (batch[m] < g) l = m + 1; else r = m; }
    int lo = l;
    r = N_NODES;
    while (l < r) { int m = (l + r) >> 1; if (batch[m] < g + 1) l = m + 1; else r = m; }
    int hi = l;

    float acc = 0.f;
    for (int n = lo; n < hi; n++) acc += agg[(size_t)n * 64 + tid];
    int cnt = hi - lo;
    float pooled = acc / (float)(cnt > 0 ? cnt : 1);

    __shared__ float sp[64];
    __shared__ float sz[32];
    sp[tid] = pooled;
    __syncthreads();

    if (tid < 32) {
        float z = lb1[tid];
#pragma unroll 8
        for (int k = 0; k < 64; k++) z += sp[k] * lw1[k * 32 + tid];
        sz[tid] = fmaxf(z, 0.f);
    }
    __syncthreads();

    if (tid < 8) {
        float o = lb2[tid];
#pragma unroll
        for (int j = 0; j < 32; j++) o += sz[j] * lw2[j * 8 + tid];
        out[g * 8 + tid] = o;
    }
}

// ---------------- launch ----------------
extern "C" void kernel_launch(void* const* d_in, const int* in_sizes, int n_in,
                              void* d_out, int out_size) {
    const float* x   = (const float*)d_in[0];
    const int*   ei  = (const int*)d_in[1];
    const int*   bat = (const int*)d_in[2];
    const float* W1  = (const float*)d_in[3];
    const float* b1  = (const float*)d_in[4];
    const float* W2  = (const float*)d_in[5];
    const float* b2  = (const float*)d_in[6];
    const float* lw1 = (const float*)d_in[7];
    const float* lb1 = (const float*)d_in[8];
    const float* lw2 = (const float*)d_in[9];
    const float* lb2 = (const float*)d_in[10];
    float* out = (float*)d_out;

    float *h, *agg;
    cudaGetSymbolAddress((void**)&h,   g_h);
    cudaGetSymbolAddress((void**)&agg, g_agg);

    // side stream + fork/join events (created once; host-side resources only)
    static cudaStream_t s2 = nullptr;
    static cudaEvent_t evFork = nullptr, evJoin = nullptr;
    if (s2 == nullptr) {
        cudaStreamCreateWithFlags(&s2, cudaStreamNonBlocking);
        cudaEventCreateWithFlags(&evFork, cudaEventDisableTiming);
        cudaEventCreateWithFlags(&evJoin, cudaEventDisableTiming);
    }

    const int nblk = (N_NODES + 255) / 256;
    const int eblk = (N_EDGES + 255) / 256;
    const int gemm_blocks = (N_NODES + 127) / 128;
    const int gath_blocks = (N_NODES * 16 + 255) / 256;

    // fork: CSR build chain on s2, GEMM1 on main stream (independent)
    cudaEventRecord(evFork, 0);
    cudaStreamWaitEvent(s2, evFork, 0);

    k_deg_init<<<nblk, 256, 0, s2>>>();
    k_deg_count<<<eblk, 256, 0, s2>>>(ei);
    k_dinv<<<nblk, 256, 0, s2>>>();
    k_scanA<<<NB_SCAN, 256, 0, s2>>>();
    k_scanB<<<1, 512, 0, s2>>>();
    k_scanC<<<nblk, 256, 0, s2>>>();
    k_fill<<<eblk, 256, 0, s2>>>(ei);

    k_gcn_gemm<false><<<gemm_blocks, 128>>>(x, W1, h);   // main stream, concurrent

    // join
    cudaEventRecord(evJoin, s2);
    cudaStreamWaitEvent(0, evJoin, 0);

    // layer 1 aggregation (needs CSR + h)
    k_gather<<<gath_blocks, 256>>>(h, b1, agg);

    // layer 2
    k_gcn_gemm<true><<<gemm_blocks, 128>>>(agg, W2, h);
    k_gather<<<gath_blocks, 256>>>(h, b2, agg);

    // pool per graph + MLP head
    k_pool_head<<<N_GRAPHS, 64>>>(agg, bat, lw1, lb1, lw2, lb2, out);
}

// round 5
// speedup vs baseline: 1.0948x; 1.0948x over previous
#include <cuda_runtime.h>

#define N_NODES  100000
#define N_EDGES  1600000
#define N_GRAPHS 1000
#define D        64
#define NB_SCAN  ((N_NODES + 255) / 256)   // 391

// ---------------- device scratch (no allocations allowed) ----------------
__device__ int   g_deg[N_NODES];
__device__ int   g_off[N_NODES];           // CSR row offsets
__device__ int   g_cursor[N_NODES];        // fill cursors
__device__ int   g_bsum[NB_SCAN];
__device__ int   g_boff[NB_SCAN];
__device__ int   g_csr[N_EDGES];           // src indices grouped by dst
__device__ float g_dinv[N_NODES];
__device__ float g_hs[(size_t)N_NODES * D];   // h * dinv[row] (pre-scaled messages)
__device__ float g_agg[(size_t)N_NODES * D];  // aggregation output

// ---------------- degree / norm ----------------
__global__ void k_deg_init() {
    int i = blockIdx.x * blockDim.x + threadIdx.x;
    if (i < N_NODES) g_deg[i] = 1;  // self-loop
}

// 4 edges per thread via int4 (N_EDGES % 4 == 0)
__global__ void k_deg_count(const int* __restrict__ ei) {
    int t = blockIdx.x * blockDim.x + threadIdx.x;
    if (t < N_EDGES / 4) {
        int4 d = ((const int4*)(ei + N_EDGES))[t];
        atomicAdd(&g_deg[d.x], 1);
        atomicAdd(&g_deg[d.y], 1);
        atomicAdd(&g_deg[d.z], 1);
        atomicAdd(&g_deg[d.w], 1);
    }
}

__global__ void k_dinv() {
    int i = blockIdx.x * blockDim.x + threadIdx.x;
    if (i < N_NODES) {
        g_dinv[i] = rsqrtf((float)g_deg[i]);
        g_cursor[i] = 0;
    }
}

// ---------------- 3-pass exclusive scan of (deg-1) into g_off ----------------
__global__ __launch_bounds__(256) void k_scanA() {
    __shared__ int s[256];
    int tid = threadIdx.x;
    int i = blockIdx.x * 256 + tid;
    int v = (i < N_NODES) ? (g_deg[i] - 1) : 0;
    s[tid] = v;
    __syncthreads();
#pragma unroll
    for (int o = 1; o < 256; o <<= 1) {
        int t = (tid >= o) ? s[tid - o] : 0;
        __syncthreads();
        s[tid] += t;
        __syncthreads();
    }
    if (i < N_NODES) g_off[i] = s[tid] - v;          // exclusive
    if (tid == 255) g_bsum[blockIdx.x] = s[255];
}

__global__ __launch_bounds__(512) void k_scanB() {
    __shared__ int s[512];
    int tid = threadIdx.x;
    int v = (tid < NB_SCAN) ? g_bsum[tid] : 0;
    s[tid] = v;
    __syncthreads();
#pragma unroll
    for (int o = 1; o < 512; o <<= 1) {
        int t = (tid >= o) ? s[tid - o] : 0;
        __syncthreads();
        s[tid] += t;
        __syncthreads();
    }
    if (tid < NB_SCAN) g_boff[tid] = s[tid] - v;     // exclusive
}

__global__ __launch_bounds__(256) void k_scanC() {
    int i = blockIdx.x * 256 + threadIdx.x;
    if (i < N_NODES) g_off[i] += g_boff[i >> 8];
}

// ---------------- CSR fill: group src indices by dst ----------------
__global__ __launch_bounds__(256) void k_fill(const int* __restrict__ ei) {
    int e = blockIdx.x * blockDim.x + threadIdx.x;
    if (e < N_EDGES) {
        int src = ei[e];
        int dst = ei[N_EDGES + e];
        int pos = g_off[dst] + atomicAdd(&g_cursor[dst], 1);
        g_csr[pos] = src;
    }
}

// ---------------- GEMM + prescale epilogue: hs = (act(in) @ W) * dinv[row] ----------------
template<bool RELU_IN>
__global__ __launch_bounds__(128) void k_gcn_gemm(const float* __restrict__ in,
                                                  const float* __restrict__ W,
                                                  float* __restrict__ hs) {
    __shared__ float Xt[64][128];   // [k][swizzled row]   32KB
    __shared__ float Ws[64][64];    // [k][col]            16KB

    const int tid = threadIdx.x;        // 0..127
    const int rowBase = blockIdx.x * 128;

    // ---- stage W ----
    {
        const float4* W4 = (const float4*)W;
        float4* Ws4 = (float4*)Ws;
#pragma unroll
        for (int i = 0; i < 8; i++) Ws4[tid + i * 128] = W4[tid + i * 128];
    }

    // ---- stage X transposed ----
#pragma unroll
    for (int i = 0; i < 16; i++) {
        int f4  = tid + i * 128;        // 0..2047
        int r   = f4 >> 4;
        int c4  = f4 & 15;
        int row = rowBase + r;
        float4 v = make_float4(0.f, 0.f, 0.f, 0.f);
        if (row < N_NODES) v = ((const float4*)in)[(size_t)row * 16 + c4];
        if (RELU_IN) {
            v.x = fmaxf(v.x, 0.f); v.y = fmaxf(v.y, 0.f);
            v.z = fmaxf(v.z, 0.f); v.w = fmaxf(v.w, 0.f);
        }
        int rsw = (((r >> 3) ^ c4) << 3) | (r & 7);
        Xt[c4 * 4 + 0][rsw] = v.x;
        Xt[c4 * 4 + 1][rsw] = v.y;
        Xt[c4 * 4 + 2][rsw] = v.z;
        Xt[c4 * 4 + 3][rsw] = v.w;
    }
    __syncthreads();

    const int rg  = tid >> 3;
    const int cg8 = (tid & 7) * 8;

    float acc[8][8];
#pragma unroll
    for (int i = 0; i < 8; i++)
#pragma unroll
        for (int j = 0; j < 8; j++) acc[i][j] = 0.f;

#pragma unroll 8
    for (int k = 0; k < 64; k++) {
        int rgx = ((rg ^ (k >> 2)) << 3);
        float4 xa = *(const float4*)&Xt[k][rgx];
        float4 xb = *(const float4*)&Xt[k][rgx + 4];
        float4 wa = *(const float4*)&Ws[k][cg8];
        float4 wb = *(const float4*)&Ws[k][cg8 + 4];
        float xv[8] = {xa.x, xa.y, xa.z, xa.w, xb.x, xb.y, xb.z, xb.w};
        float wv[8] = {wa.x, wa.y, wa.z, wa.w, wb.x, wb.y, wb.z, wb.w};
#pragma unroll
        for (int i = 0; i < 8; i++)
#pragma unroll
            for (int j = 0; j < 8; j++)
                acc[i][j] += xv[i] * wv[j];
    }

    // ---- epilogue: hs = out * dinv[row] ----
#pragma unroll
    for (int i = 0; i < 8; i++) {
        int row = rowBase + rg * 8 + i;
        if (row >= N_NODES) break;
        float di = g_dinv[row];
        size_t o = (size_t)row * 16 + (cg8 >> 2);
        ((float4*)hs)[o + 0] = make_float4(acc[i][0] * di, acc[i][1] * di,
                                           acc[i][2] * di, acc[i][3] * di);
        ((float4*)hs)[o + 1] = make_float4(acc[i][4] * di, acc[i][5] * di,
                                           acc[i][6] * di, acc[i][7] * di);
    }
}

// ---------------- CSR gather (write-only output) ----------------
// agg[n] = dinv[n] * ( hs[n]  +  sum_{s in csr[n]} hs[s] ) + b
//   (hs[n] = dinv[n]*h[n], so dinv*hs[n] = dinv^2*h[n] = self-loop term)
__global__ __launch_bounds__(256) void k_gather(const float* __restrict__ hs,
                                                const float* __restrict__ bias,
                                                float* __restrict__ agg) {
    int t = blockIdx.x * blockDim.x + threadIdx.x;
    int node = t >> 4;
    int lane = t & 15;
    if (node >= N_NODES) return;

    int start = g_off[node];
    int cnt   = g_deg[node] - 1;

    // self term seeds one accumulator chain
    float4 a0 = ((const float4*)hs)[(size_t)node * 16 + lane];
    float4 a1 = make_float4(0.f, 0.f, 0.f, 0.f);

    int i = 0;
    for (; i + 4 <= cnt; i += 4) {
        int s0 = g_csr[start + i + 0];
        int s1 = g_csr[start + i + 1];
        int s2 = g_csr[start + i + 2];
        int s3 = g_csr[start + i + 3];
        float4 v0 = ((const float4*)hs)[(size_t)s0 * 16 + lane];
        float4 v1 = ((const float4*)hs)[(size_t)s1 * 16 + lane];
        float4 v2 = ((const float4*)hs)[(size_t)s2 * 16 + lane];
        float4 v3 = ((const float4*)hs)[(size_t)s3 * 16 + lane];
        a0.x += v0.x; a0.y += v0.y; a0.z += v0.z; a0.w += v0.w;
        a1.x += v1.x; a1.y += v1.y; a1.z += v1.z; a1.w += v1.w;
        a0.x += v2.x; a0.y += v2.y; a0.z += v2.z; a0.w += v2.w;
        a1.x += v3.x; a1.y += v3.y; a1.z += v3.z; a1.w += v3.w;
    }
    for (; i < cnt; i++) {
        int s0 = g_csr[start + i];
        float4 v0 = ((const float4*)hs)[(size_t)s0 * 16 + lane];
        a0.x += v0.x; a0.y += v0.y; a0.z += v0.z; a0.w += v0.w;
    }

    float dv = g_dinv[node];
    float4 bv = ((const float4*)bias)[lane];
    float4 o;
    o.x = dv * (a0.x + a1.x) + bv.x;
    o.y = dv * (a0.y + a1.y) + bv.y;
    o.z = dv * (a0.z + a1.z) + bv.z;
    o.w = dv * (a0.w + a1.w) + bv.w;
    ((float4*)agg)[(size_t)node * 16 + lane] = o;
}

// ---------------- fused mean-pool (batch is sorted) + MLP head ----------------
__global__ __launch_bounds__(64) void k_pool_head(const float* __restrict__ agg,
                                                  const int* __restrict__ batch,
                                                  const float* __restrict__ lw1,
                                                  const float* __restrict__ lb1,
                                                  const float* __restrict__ lw2,
                                                  const float* __restrict__ lb2,
                                                  float* __restrict__ out) {
    int g = blockIdx.x;
    int tid = threadIdx.x;  // 64

    int l = 0, r = N_NODES;
    while (l < r) { int m = (l + r) >> 1; if (batch[m] < g) l = m + 1; else r = m; }
    int lo = l;
    r = N_NODES;
    while (l < r) { int m = (l + r) >> 1; if (batch[m] < g + 1) l = m + 1; else r = m; }
    int hi = l;

    float acc = 0.f;
    for (int n = lo; n < hi; n++) acc += agg[(size_t)n * 64 + tid];
    int cnt = hi - lo;
    float pooled = acc / (float)(cnt > 0 ? cnt : 1);

    __shared__ float sp[64];
    __shared__ float sz[32];
    sp[tid] = pooled;
    __syncthreads();

    if (tid < 32) {
        float z = lb1[tid];
#pragma unroll 8
        for (int k = 0; k < 64; k++) z += sp[k] * lw1[k * 32 + tid];
        sz[tid] = fmaxf(z, 0.f);
    }
    __syncthreads();

    if (tid < 8) {
        float o = lb2[tid];
#pragma unroll
        for (int j = 0; j < 32; j++) o += sz[j] * lw2[j * 8 + tid];
        out[g * 8 + tid] = o;
    }
}

// ---------------- launch ----------------
extern "C" void kernel_launch(void* const* d_in, const int* in_sizes, int n_in,
                              void* d_out, int out_size) {
    const float* x   = (const float*)d_in[0];
    const int*   ei  = (const int*)d_in[1];
    const int*   bat = (const int*)d_in[2];
    const float* W1  = (const float*)d_in[3];
    const float* b1  = (const float*)d_in[4];
    const float* W2  = (const float*)d_in[5];
    const float* b2  = (const float*)d_in[6];
    const float* lw1 = (const float*)d_in[7];
    const float* lb1 = (const float*)d_in[8];
    const float* lw2 = (const float*)d_in[9];
    const float* lb2 = (const float*)d_in[10];
    float* out = (float*)d_out;

    float *hs, *agg;
    cudaGetSymbolAddress((void**)&hs,  g_hs);
    cudaGetSymbolAddress((void**)&agg, g_agg);

    // side stream + fork/join events (host-side resources, created once)
    static cudaStream_t s2 = nullptr;
    static cudaEvent_t evFork = nullptr, evJoin = nullptr;
    if (s2 == nullptr) {
        cudaStreamCreateWithFlags(&s2, cudaStreamNonBlocking);
        cudaEventCreateWithFlags(&evFork, cudaEventDisableTiming);
        cudaEventCreateWithFlags(&evJoin, cudaEventDisableTiming);
    }

    const int nblk = (N_NODES + 255) / 256;
    const int eblk = (N_EDGES + 255) / 256;
    const int gemm_blocks = (N_NODES + 127) / 128;
    const int gath_blocks = (N_NODES * 16 + 255) / 256;

    // serial prefix: degrees + dinv (GEMM1 epilogue needs dinv)
    k_deg_init<<<nblk, 256>>>();
    k_deg_count<<<(N_EDGES / 4 + 255) / 256, 256>>>(ei);
    k_dinv<<<nblk, 256>>>();

    // fork: scan+fill on s2 (memory-bound) || GEMM1 on main (fma-bound)
    cudaEventRecord(evFork, 0);
    cudaStreamWaitEvent(s2, evFork, 0);

    k_scanA<<<NB_SCAN, 256, 0, s2>>>();
    k_scanB<<<1, 512, 0, s2>>>();
    k_scanC<<<nblk, 256, 0, s2>>>();
    k_fill<<<eblk, 256, 0, s2>>>(ei);

    k_gcn_gemm<false><<<gemm_blocks, 128>>>(x, W1, hs);   // concurrent

    // join
    cudaEventRecord(evJoin, s2);
    cudaStreamWaitEvent(0, evJoin, 0);

    // layer 1 aggregation (needs CSR + hs)
    k_gather<<<gath_blocks, 256>>>(hs, b1, agg);

    // layer 2
    k_gcn_gemm<true><<<gemm_blocks, 128>>>(agg, W2, hs);
    k_gather<<<gath_blocks, 256>>>(hs, b2, agg);

    // pool per graph + MLP head
    k_pool_head<<<N_GRAPHS, 64>>>(agg, bat, lw1, lb1, lw2, lb2, out);
}

// round 6
// speedup vs baseline: 1.2097x; 1.1050x over previous
#include <cuda_runtime.h>
#include <cuda_fp16.h>

#define N_NODES  100000
#define N_EDGES  1600000
#define N_GRAPHS 1000
#define D        64
#define NB_SCAN  ((N_NODES + 255) / 256)   // 391

// ---------------- device scratch (no allocations allowed) ----------------
__device__ int    g_deg[N_NODES];
__device__ int    g_off[N_NODES];           // CSR row offsets
__device__ int    g_cursor[N_NODES];        // fill cursors
__device__ int    g_bsum[NB_SCAN];
__device__ int    g_boff[NB_SCAN];
__device__ int    g_csr[N_EDGES];           // src indices grouped by dst
__device__ float  g_dinv[N_NODES];
__device__ __half g_hs[(size_t)N_NODES * D];  // fp16 prescaled messages h*dinv[row]
__device__ float  g_agg[(size_t)N_NODES * D]; // fp32 aggregation output

// ---------------- degree / norm ----------------
__global__ void k_deg_init() {
    int i = blockIdx.x * blockDim.x + threadIdx.x;
    if (i < N_NODES) g_deg[i] = 1;  // self-loop
}

__global__ void k_deg_count(const int* __restrict__ ei) {
    int t = blockIdx.x * blockDim.x + threadIdx.x;
    if (t < N_EDGES / 4) {
        int4 d = ((const int4*)(ei + N_EDGES))[t];
        atomicAdd(&g_deg[d.x], 1);
        atomicAdd(&g_deg[d.y], 1);
        atomicAdd(&g_deg[d.z], 1);
        atomicAdd(&g_deg[d.w], 1);
    }
}

__global__ void k_dinv() {
    int i = blockIdx.x * blockDim.x + threadIdx.x;
    if (i < N_NODES) {
        g_dinv[i] = rsqrtf((float)g_deg[i]);
        g_cursor[i] = 0;
    }
}

// ---------------- 3-pass exclusive scan of (deg-1) into g_off ----------------
__global__ __launch_bounds__(256) void k_scanA() {
    __shared__ int s[256];
    int tid = threadIdx.x;
    int i = blockIdx.x * 256 + tid;
    int v = (i < N_NODES) ? (g_deg[i] - 1) : 0;
    s[tid] = v;
    __syncthreads();
#pragma unroll
    for (int o = 1; o < 256; o <<= 1) {
        int t = (tid >= o) ? s[tid - o] : 0;
        __syncthreads();
        s[tid] += t;
        __syncthreads();
    }
    if (i < N_NODES) g_off[i] = s[tid] - v;          // exclusive
    if (tid == 255) g_bsum[blockIdx.x] = s[255];
}

__global__ __launch_bounds__(512) void k_scanB() {
    __shared__ int s[512];
    int tid = threadIdx.x;
    int v = (tid < NB_SCAN) ? g_bsum[tid] : 0;
    s[tid] = v;
    __syncthreads();
#pragma unroll
    for (int o = 1; o < 512; o <<= 1) {
        int t = (tid >= o) ? s[tid - o] : 0;
        __syncthreads();
        s[tid] += t;
        __syncthreads();
    }
    if (tid < NB_SCAN) g_boff[tid] = s[tid] - v;     // exclusive
}

__global__ __launch_bounds__(256) void k_scanC() {
    int i = blockIdx.x * 256 + threadIdx.x;
    if (i < N_NODES) g_off[i] += g_boff[i >> 8];
}

// ---------------- CSR fill: group src indices by dst ----------------
__global__ __launch_bounds__(256) void k_fill(const int* __restrict__ ei) {
    int e = blockIdx.x * blockDim.x + threadIdx.x;
    if (e < N_EDGES) {
        int src = ei[e];
        int dst = ei[N_EDGES + e];
        int pos = g_off[dst] + atomicAdd(&g_cursor[dst], 1);
        g_csr[pos] = src;
    }
}

// ---------------- GEMM + prescale epilogue: hs = fp16( (act(in) @ W) * dinv[row] ) ----------------
template<bool RELU_IN>
__global__ __launch_bounds__(128) void k_gcn_gemm(const float* __restrict__ in,
                                                  const float* __restrict__ W,
                                                  __half* __restrict__ hs) {
    __shared__ float Xt[64][128];   // [k][swizzled row]   32KB
    __shared__ float Ws[64][64];    // [k][col]            16KB

    const int tid = threadIdx.x;        // 0..127
    const int rowBase = blockIdx.x * 128;

    // ---- stage W ----
    {
        const float4* W4 = (const float4*)W;
        float4* Ws4 = (float4*)Ws;
#pragma unroll
        for (int i = 0; i < 8; i++) Ws4[tid + i * 128] = W4[tid + i * 128];
    }

    // ---- stage X transposed ----
#pragma unroll
    for (int i = 0; i < 16; i++) {
        int f4  = tid + i * 128;        // 0..2047
        int r   = f4 >> 4;
        int c4  = f4 & 15;
        int row = rowBase + r;
        float4 v = make_float4(0.f, 0.f, 0.f, 0.f);
        if (row < N_NODES) v = ((const float4*)in)[(size_t)row * 16 + c4];
        if (RELU_IN) {
            v.x = fmaxf(v.x, 0.f); v.y = fmaxf(v.y, 0.f);
            v.z = fmaxf(v.z, 0.f); v.w = fmaxf(v.w, 0.f);
        }
        int rsw = (((r >> 3) ^ c4) << 3) | (r & 7);
        Xt[c4 * 4 + 0][rsw] = v.x;
        Xt[c4 * 4 + 1][rsw] = v.y;
        Xt[c4 * 4 + 2][rsw] = v.z;
        Xt[c4 * 4 + 3][rsw] = v.w;
    }
    __syncthreads();

    const int rg  = tid >> 3;
    const int cg8 = (tid & 7) * 8;

    float acc[8][8];
#pragma unroll
    for (int i = 0; i < 8; i++)
#pragma unroll
        for (int j = 0; j < 8; j++) acc[i][j] = 0.f;

#pragma unroll 8
    for (int k = 0; k < 64; k++) {
        int rgx = ((rg ^ (k >> 2)) << 3);
        float4 xa = *(const float4*)&Xt[k][rgx];
        float4 xb = *(const float4*)&Xt[k][rgx + 4];
        float4 wa = *(const float4*)&Ws[k][cg8];
        float4 wb = *(const float4*)&Ws[k][cg8 + 4];
        float xv[8] = {xa.x, xa.y, xa.z, xa.w, xb.x, xb.y, xb.z, xb.w};
        float wv[8] = {wa.x, wa.y, wa.z, wa.w, wb.x, wb.y, wb.z, wb.w};
#pragma unroll
        for (int i = 0; i < 8; i++)
#pragma unroll
            for (int j = 0; j < 8; j++)
                acc[i][j] += xv[i] * wv[j];
    }

    // ---- epilogue: hs = fp16(out * dinv[row]), one uint4 (8 halves) per row ----
#pragma unroll
    for (int i = 0; i < 8; i++) {
        int row = rowBase + rg * 8 + i;
        if (row >= N_NODES) break;
        float di = g_dinv[row];
        __half2 ph[4];
        ph[0] = __floats2half2_rn(acc[i][0] * di, acc[i][1] * di);
        ph[1] = __floats2half2_rn(acc[i][2] * di, acc[i][3] * di);
        ph[2] = __floats2half2_rn(acc[i][4] * di, acc[i][5] * di);
        ph[3] = __floats2half2_rn(acc[i][6] * di, acc[i][7] * di);
        ((uint4*)hs)[(size_t)row * 8 + (cg8 >> 3)] = *(uint4*)ph;
    }
}

// ---------------- fp16 accumulate helper: a[0..7] += unpack(v) ----------------
__device__ __forceinline__ void acc_u4(float* a, uint4 v) {
    float2 f0 = __half22float2(*(__half2*)&v.x);
    float2 f1 = __half22float2(*(__half2*)&v.y);
    float2 f2 = __half22float2(*(__half2*)&v.z);
    float2 f3 = __half22float2(*(__half2*)&v.w);
    a[0] += f0.x; a[1] += f0.y; a[2] += f1.x; a[3] += f1.y;
    a[4] += f2.x; a[5] += f2.y; a[6] += f3.x; a[7] += f3.y;
}

// ---------------- CSR gather (fp16 in, fp32 out, write-only) ----------------
// agg[n] = dinv[n] * ( hs[n] + sum_{s in csr[n]} hs[s] ) + b
// 8 lanes per node; each lane owns 8 feature dims (one uint4 of halves).
__global__ __launch_bounds__(256) void k_gather(const __half* __restrict__ hs,
                                                const float* __restrict__ bias,
                                                float* __restrict__ agg) {
    int t = blockIdx.x * blockDim.x + threadIdx.x;
    int node = t >> 3;
    int lane = t & 7;
    if (node >= N_NODES) return;

    const uint4* hs4 = (const uint4*)hs;
    int start = g_off[node];
    int cnt   = g_deg[node] - 1;

    float a[8] = {0.f, 0.f, 0.f, 0.f, 0.f, 0.f, 0.f, 0.f};
    float b[8] = {0.f, 0.f, 0.f, 0.f, 0.f, 0.f, 0.f, 0.f};

    // self term
    acc_u4(a, hs4[(size_t)node * 8 + lane]);

    int i = 0;
    for (; i + 4 <= cnt; i += 4) {
        int s0 = g_csr[start + i + 0];
        int s1 = g_csr[start + i + 1];
        int s2 = g_csr[start + i + 2];
        int s3 = g_csr[start + i + 3];
        uint4 v0 = hs4[(size_t)s0 * 8 + lane];
        uint4 v1 = hs4[(size_t)s1 * 8 + lane];
        uint4 v2 = hs4[(size_t)s2 * 8 + lane];
        uint4 v3 = hs4[(size_t)s3 * 8 + lane];
        acc_u4(a, v0);
        acc_u4(b, v1);
        acc_u4(a, v2);
        acc_u4(b, v3);
    }
    for (; i < cnt; i++) {
        int s0 = g_csr[start + i];
        acc_u4(a, hs4[(size_t)s0 * 8 + lane]);
    }

    float dv = g_dinv[node];
    float4 bv0 = ((const float4*)bias)[lane * 2 + 0];
    float4 bv1 = ((const float4*)bias)[lane * 2 + 1];
    float4 o0, o1;
    o0.x = dv * (a[0] + b[0]) + bv0.x;
    o0.y = dv * (a[1] + b[1]) + bv0.y;
    o0.z = dv * (a[2] + b[2]) + bv0.z;
    o0.w = dv * (a[3] + b[3]) + bv0.w;
    o1.x = dv * (a[4] + b[4]) + bv1.x;
    o1.y = dv * (a[5] + b[5]) + bv1.y;
    o1.z = dv * (a[6] + b[6]) + bv1.w * 0.f + bv1.z;  // keep ordering simple
    o1.w = dv * (a[7] + b[7]) + bv1.w;
    float4* op = (float4*)(agg + (size_t)node * 64 + lane * 8);
    op[0] = o0;
    op[1] = o1;
}

// ---------------- fused mean-pool (batch is sorted) + MLP head ----------------
__global__ __launch_bounds__(64) void k_pool_head(const float* __restrict__ agg,
                                                  const int* __restrict__ batch,
                                                  const float* __restrict__ lw1,
                                                  const float* __restrict__ lb1,
                                                  const float* __restrict__ lw2,
                                                  const float* __restrict__ lb2,
                                                  float* __restrict__ out) {
    int g = blockIdx.x;
    int tid = threadIdx.x;  // 64

    int l = 0, r = N_NODES;
    while (l < r) { int m = (l + r) >> 1; if (batch[m] < g) l = m + 1; else r = m; }
    int lo = l;
    r = N_NODES;
    while (l < r) { int m = (l + r) >> 1; if (batch[m] < g + 1) l = m + 1; else r = m; }
    int hi = l;

    float acc = 0.f;
    for (int n = lo; n < hi; n++) acc += agg[(size_t)n * 64 + tid];
    int cnt = hi - lo;
    float pooled = acc / (float)(cnt > 0 ? cnt : 1);

    __shared__ float sp[64];
    __shared__ float sz[32];
    sp[tid] = pooled;
    __syncthreads();

    if (tid < 32) {
        float z = lb1[tid];
#pragma unroll 8
        for (int k = 0; k < 64; k++) z += sp[k] * lw1[k * 32 + tid];
        sz[tid] = fmaxf(z, 0.f);
    }
    __syncthreads();

    if (tid < 8) {
        float o = lb2[tid];
#pragma unroll
        for (int j = 0; j < 32; j++) o += sz[j] * lw2[j * 8 + tid];
        out[g * 8 + tid] = o;
    }
}

// ---------------- launch ----------------
extern "C" void kernel_launch(void* const* d_in, const int* in_sizes, int n_in,
                              void* d_out, int out_size) {
    const float* x   = (const float*)d_in[0];
    const int*   ei  = (const int*)d_in[1];
    const int*   bat = (const int*)d_in[2];
    const float* W1  = (const float*)d_in[3];
    const float* b1  = (const float*)d_in[4];
    const float* W2  = (const float*)d_in[5];
    const float* b2  = (const float*)d_in[6];
    const float* lw1 = (const float*)d_in[7];
    const float* lb1 = (const float*)d_in[8];
    const float* lw2 = (const float*)d_in[9];
    const float* lb2 = (const float*)d_in[10];
    float* out = (float*)d_out;

    __half* hs;
    float* agg;
    cudaGetSymbolAddress((void**)&hs,  g_hs);
    cudaGetSymbolAddress((void**)&agg, g_agg);

    static cudaStream_t s2 = nullptr;
    static cudaEvent_t evFork = nullptr, evJoin = nullptr;
    if (s2 == nullptr) {
        cudaStreamCreateWithFlags(&s2, cudaStreamNonBlocking);
        cudaEventCreateWithFlags(&evFork, cudaEventDisableTiming);
        cudaEventCreateWithFlags(&evJoin, cudaEventDisableTiming);
    }

    const int nblk = (N_NODES + 255) / 256;
    const int eblk = (N_EDGES + 255) / 256;
    const int gemm_blocks = (N_NODES + 127) / 128;
    const int gath_blocks = (N_NODES * 8 + 255) / 256;

    // serial prefix: degrees + dinv (GEMM1 epilogue needs dinv)
    k_deg_init<<<nblk, 256>>>();
    k_deg_count<<<(N_EDGES / 4 + 255) / 256, 256>>>(ei);
    k_dinv<<<nblk, 256>>>();

    // fork: scan+fill on s2 || GEMM1 on main
    cudaEventRecord(evFork, 0);
    cudaStreamWaitEvent(s2, evFork, 0);

    k_scanA<<<NB_SCAN, 256, 0, s2>>>();
    k_scanB<<<1, 512, 0, s2>>>();
    k_scanC<<<nblk, 256, 0, s2>>>();
    k_fill<<<eblk, 256, 0, s2>>>(ei);

    k_gcn_gemm<false><<<gemm_blocks, 128>>>(x, W1, hs);   // concurrent

    cudaEventRecord(evJoin, s2);
    cudaStreamWaitEvent(0, evJoin, 0);

    // layer 1 aggregation
    k_gather<<<gath_blocks, 256>>>(hs, b1, agg);

    // layer 2
    k_gcn_gemm<true><<<gemm_blocks, 128>>>(agg, W2, hs);
    k_gather<<<gath_blocks, 256>>>(hs, b2, agg);

    // pool per graph + MLP head
    k_pool_head<<<N_GRAPHS, 64>>>(agg, bat, lw1, lb1, lw2, lb2, out);
}

// round 7
// speedup vs baseline: 1.4305x; 1.1825x over previous
#include <cuda_runtime.h>
#include <cuda_fp16.h>
#include <mma.h>

using namespace nvcuda;

#define N_NODES  100000
#define N_EDGES  1600000
#define N_GRAPHS 1000
#define D        64
#define NB_SCAN  ((N_NODES + 255) / 256)   // 391

// ---------------- device scratch (no allocations allowed) ----------------
__device__ int    g_deg[N_NODES];
__device__ int    g_off[N_NODES];           // CSR row offsets
__device__ int    g_cursor[N_NODES];        // fill cursors
__device__ int    g_bsum[NB_SCAN];
__device__ int    g_boff[NB_SCAN];
__device__ int    g_csr[N_EDGES];           // src indices grouped by dst
__device__ float  g_dinv[N_NODES];
__device__ __half g_hs[(size_t)N_NODES * D];  // fp16 prescaled messages h*dinv[row]
__device__ float  g_agg[(size_t)N_NODES * D]; // fp32 aggregation output

// ---------------- degree / norm ----------------
__global__ void k_deg_init() {
    int i = blockIdx.x * blockDim.x + threadIdx.x;
    if (i < N_NODES) g_deg[i] = 1;  // self-loop
}

__global__ void k_deg_count(const int* __restrict__ ei) {
    int t = blockIdx.x * blockDim.x + threadIdx.x;
    if (t < N_EDGES / 4) {
        int4 d = ((const int4*)(ei + N_EDGES))[t];
        atomicAdd(&g_deg[d.x], 1);
        atomicAdd(&g_deg[d.y], 1);
        atomicAdd(&g_deg[d.z], 1);
        atomicAdd(&g_deg[d.w], 1);
    }
}

__global__ void k_dinv() {
    int i = blockIdx.x * blockDim.x + threadIdx.x;
    if (i < N_NODES) {
        g_dinv[i] = rsqrtf((float)g_deg[i]);
        g_cursor[i] = 0;
    }
}

// ---------------- 3-pass exclusive scan of (deg-1) into g_off ----------------
__global__ __launch_bounds__(256) void k_scanA() {
    __shared__ int s[256];
    int tid = threadIdx.x;
    int i = blockIdx.x * 256 + tid;
    int v = (i < N_NODES) ? (g_deg[i] - 1) : 0;
    s[tid] = v;
    __syncthreads();
#pragma unroll
    for (int o = 1; o < 256; o <<= 1) {
        int t = (tid >= o) ? s[tid - o] : 0;
        __syncthreads();
        s[tid] += t;
        __syncthreads();
    }
    if (i < N_NODES) g_off[i] = s[tid] - v;          // exclusive
    if (tid == 255) g_bsum[blockIdx.x] = s[255];
}

__global__ __launch_bounds__(512) void k_scanB() {
    __shared__ int s[512];
    int tid = threadIdx.x;
    int v = (tid < NB_SCAN) ? g_bsum[tid] : 0;
    s[tid] = v;
    __syncthreads();
#pragma unroll
    for (int o = 1; o < 512; o <<= 1) {
        int t = (tid >= o) ? s[tid - o] : 0;
        __syncthreads();
        s[tid] += t;
        __syncthreads();
    }
    if (tid < NB_SCAN) g_boff[tid] = s[tid] - v;     // exclusive
}

__global__ __launch_bounds__(256) void k_scanC() {
    int i = blockIdx.x * 256 + threadIdx.x;
    if (i < N_NODES) g_off[i] += g_boff[i >> 8];
}

// ---------------- CSR fill: group src indices by dst ----------------
__global__ __launch_bounds__(256) void k_fill(const int* __restrict__ ei) {
    int e = blockIdx.x * blockDim.x + threadIdx.x;
    if (e < N_EDGES) {
        int src = ei[e];
        int dst = ei[N_EDGES + e];
        int pos = g_off[dst] + atomicAdd(&g_cursor[dst], 1);
        g_csr[pos] = src;
    }
}

// ---------------- tensor-core GEMM: hs = fp16( (act(in)*dinv[row]) @ W ) ----------------
// dinv scale applied on INPUT rows (commutes with GEMM; relu commutes since dinv>0).
// 256 threads = 8 warps; 128 rows x 64 cols per block; wmma m16n16k16, fp32 accum.
template<bool RELU_IN>
__global__ __launch_bounds__(256) void k_gcn_gemm(const float* __restrict__ in,
                                                  const float* __restrict__ W,
                                                  __half* __restrict__ hs) {
    __shared__ __align__(16) char smem_raw[128 * 68 * 4];   // 34816B, unioned
    __half (*Xh)[72] = (__half(*)[72])smem_raw;              // 128x72 fp16 (18432B)
    __half (*Wh)[72] = (__half(*)[72])(smem_raw + 18432);    // 64x72  fp16 ( 9216B)
    float  (*Out)[68] = (float(*)[68])smem_raw;              // 128x68 fp32 (after sync)

    const int tid = threadIdx.x;
    const int rowBase = blockIdx.x * 128;

    // ---- stage W as fp16 ----
#pragma unroll
    for (int i = 0; i < 4; i++) {
        int f4 = tid + i * 256;         // 0..1023
        int r  = f4 >> 4;
        int c4 = f4 & 15;
        float4 v = ((const float4*)W)[f4];
        __half2 h0 = __floats2half2_rn(v.x, v.y);
        __half2 h1 = __floats2half2_rn(v.z, v.w);
        __half2* p = (__half2*)&Wh[r][c4 * 4];
        p[0] = h0; p[1] = h1;
    }

    // ---- stage X as fp16, scaled by dinv[row], optional relu ----
#pragma unroll
    for (int i = 0; i < 8; i++) {
        int f4  = tid + i * 256;        // 0..2047
        int r   = f4 >> 4;              // 0..127
        int c4  = f4 & 15;
        int row = rowBase + r;
        float4 v = make_float4(0.f, 0.f, 0.f, 0.f);
        float di = 0.f;
        if (row < N_NODES) {
            v = ((const float4*)in)[(size_t)row * 16 + c4];
            di = g_dinv[row];
        }
        if (RELU_IN) {
            v.x = fmaxf(v.x, 0.f); v.y = fmaxf(v.y, 0.f);
            v.z = fmaxf(v.z, 0.f); v.w = fmaxf(v.w, 0.f);
        }
        __half2 h0 = __floats2half2_rn(v.x * di, v.y * di);
        __half2 h1 = __floats2half2_rn(v.z * di, v.w * di);
        __half2* p = (__half2*)&Xh[r][c4 * 4];
        p[0] = h0; p[1] = h1;
    }
    __syncthreads();

    // ---- wmma compute: warp w owns rows [w*16, w*16+16), all 4 col groups ----
    const int w = tid >> 5;
    wmma::fragment<wmma::accumulator, 16, 16, 16, float> c[4];
#pragma unroll
    for (int cg = 0; cg < 4; cg++) wmma::fill_fragment(c[cg], 0.f);

#pragma unroll
    for (int k = 0; k < 4; k++) {
        wmma::fragment<wmma::matrix_a, 16, 16, 16, __half, wmma::row_major> a;
        wmma::load_matrix_sync(a, &Xh[w * 16][k * 16], 72);
#pragma unroll
        for (int cg = 0; cg < 4; cg++) {
            wmma::fragment<wmma::matrix_b, 16, 16, 16, __half, wmma::row_major> b;
            wmma::load_matrix_sync(b, &Wh[k * 16][cg * 16], 72);
            wmma::mma_sync(c[cg], a, b, c[cg]);
        }
    }
    __syncthreads();   // staging reads done; safe to overwrite with Out

#pragma unroll
    for (int cg = 0; cg < 4; cg++)
        wmma::store_matrix_sync(&Out[w * 16][cg * 16], c[cg], 68, wmma::mem_row_major);
    __syncthreads();

    // ---- write hs: fp32 smem -> fp16 global, one uint4 (8 halves) per write ----
#pragma unroll
    for (int i = 0; i < 4; i++) {
        int idx = tid + i * 256;        // 0..1023
        int r   = idx >> 3;             // 0..127
        int q   = idx & 7;              // uint4 slot (8 halves = 8 floats)
        int row = rowBase + r;
        if (row < N_NODES) {
            const float* src = &Out[r][q * 8];
            __half2 ph[4];
            ph[0] = __floats2half2_rn(src[0], src[1]);
            ph[1] = __floats2half2_rn(src[2], src[3]);
            ph[2] = __floats2half2_rn(src[4], src[5]);
            ph[3] = __floats2half2_rn(src[6], src[7]);
            ((uint4*)hs)[(size_t)row * 8 + q] = *(uint4*)ph;
        }
    }
}

// ---------------- fp16 accumulate helper: a[0..7] += unpack(v) ----------------
__device__ __forceinline__ void acc_u4(float* a, uint4 v) {
    float2 f0 = __half22float2(*(__half2*)&v.x);
    float2 f1 = __half22float2(*(__half2*)&v.y);
    float2 f2 = __half22float2(*(__half2*)&v.z);
    float2 f3 = __half22float2(*(__half2*)&v.w);
    a[0] += f0.x; a[1] += f0.y; a[2] += f1.x; a[3] += f1.y;
    a[4] += f2.x; a[5] += f2.y; a[6] += f3.x; a[7] += f3.y;
}

// ---------------- CSR gather (fp16 in, fp32 out, write-only) ----------------
// agg[n] = dinv[n] * ( hs[n] + sum_{s in csr[n]} hs[s] ) + b
__global__ __launch_bounds__(256) void k_gather(const __half* __restrict__ hs,
                                                const float* __restrict__ bias,
                                                float* __restrict__ agg) {
    int t = blockIdx.x * blockDim.x + threadIdx.x;
    int node = t >> 3;
    int lane = t & 7;
    if (node >= N_NODES) return;

    const uint4* hs4 = (const uint4*)hs;
    int start = g_off[node];
    int cnt   = g_deg[node] - 1;

    float a[8] = {0.f, 0.f, 0.f, 0.f, 0.f, 0.f, 0.f, 0.f};
    float b[8] = {0.f, 0.f, 0.f, 0.f, 0.f, 0.f, 0.f, 0.f};

    // self term
    acc_u4(a, hs4[(size_t)node * 8 + lane]);

    int i = 0;
    for (; i + 4 <= cnt; i += 4) {
        int s0 = g_csr[start + i + 0];
        int s1 = g_csr[start + i + 1];
        int s2 = g_csr[start + i + 2];
        int s3 = g_csr[start + i + 3];
        uint4 v0 = hs4[(size_t)s0 * 8 + lane];
        uint4 v1 = hs4[(size_t)s1 * 8 + lane];
        uint4 v2 = hs4[(size_t)s2 * 8 + lane];
        uint4 v3 = hs4[(size_t)s3 * 8 + lane];
        acc_u4(a, v0);
        acc_u4(b, v1);
        acc_u4(a, v2);
        acc_u4(b, v3);
    }
    for (; i < cnt; i++) {
        int s0 = g_csr[start + i];
        acc_u4(a, hs4[(size_t)s0 * 8 + lane]);
    }

    float dv = g_dinv[node];
    float4 bv0 = ((const float4*)bias)[lane * 2 + 0];
    float4 bv1 = ((const float4*)bias)[lane * 2 + 1];
    float4 o0, o1;
    o0.x = dv * (a[0] + b[0]) + bv0.x;
    o0.y = dv * (a[1] + b[1]) + bv0.y;
    o0.z = dv * (a[2] + b[2]) + bv0.z;
    o0.w = dv * (a[3] + b[3]) + bv0.w;
    o1.x = dv * (a[4] + b[4]) + bv1.x;
    o1.y = dv * (a[5] + b[5]) + bv1.y;
    o1.z = dv * (a[6] + b[6]) + bv1.z;
    o1.w = dv * (a[7] + b[7]) + bv1.w;
    float4* op = (float4*)(agg + (size_t)node * 64 + lane * 8);
    op[0] = o0;
    op[1] = o1;
}

// ---------------- fused mean-pool (batch is sorted) + MLP head ----------------
__global__ __launch_bounds__(64) void k_pool_head(const float* __restrict__ agg,
                                                  const int* __restrict__ batch,
                                                  const float* __restrict__ lw1,
                                                  const float* __restrict__ lb1,
                                                  const float* __restrict__ lw2,
                                                  const float* __restrict__ lb2,
                                                  float* __restrict__ out) {
    int g = blockIdx.x;
    int tid = threadIdx.x;  // 64

    int l = 0, r = N_NODES;
    while (l < r) { int m = (l + r) >> 1; if (batch[m] < g) l = m + 1; else r = m; }
    int lo = l;
    r = N_NODES;
    while (l < r) { int m = (l + r) >> 1; if (batch[m] < g + 1) l = m + 1; else r = m; }
    int hi = l;

    float acc = 0.f;
    for (int n = lo; n < hi; n++) acc += agg[(size_t)n * 64 + tid];
    int cnt = hi - lo;
    float pooled = acc / (float)(cnt > 0 ? cnt : 1);

    __shared__ float sp[64];
    __shared__ float sz[32];
    sp[tid] = pooled;
    __syncthreads();

    if (tid < 32) {
        float z = lb1[tid];
#pragma unroll 8
        for (int k = 0; k < 64; k++) z += sp[k] * lw1[k * 32 + tid];
        sz[tid] = fmaxf(z, 0.f);
    }
    __syncthreads();

    if (tid < 8) {
        float o = lb2[tid];
#pragma unroll
        for (int j = 0; j < 32; j++) o += sz[j] * lw2[j * 8 + tid];
        out[g * 8 + tid] = o;
    }
}

// ---------------- launch ----------------
extern "C" void kernel_launch(void* const* d_in, const int* in_sizes, int n_in,
                              void* d_out, int out_size) {
    const float* x   = (const float*)d_in[0];
    const int*   ei  = (const int*)d_in[1];
    const int*   bat = (const int*)d_in[2];
    const float* W1  = (const float*)d_in[3];
    const float* b1  = (const float*)d_in[4];
    const float* W2  = (const float*)d_in[5];
    const float* b2  = (const float*)d_in[6];
    const float* lw1 = (const float*)d_in[7];
    const float* lb1 = (const float*)d_in[8];
    const float* lw2 = (const float*)d_in[9];
    const float* lb2 = (const float*)d_in[10];
    float* out = (float*)d_out;

    __half* hs;
    float* agg;
    cudaGetSymbolAddress((void**)&hs,  g_hs);
    cudaGetSymbolAddress((void**)&agg, g_agg);

    static cudaStream_t s2 = nullptr;
    static cudaEvent_t evFork = nullptr, evJoin = nullptr;
    if (s2 == nullptr) {
        cudaStreamCreateWithFlags(&s2, cudaStreamNonBlocking);
        cudaEventCreateWithFlags(&evFork, cudaEventDisableTiming);
        cudaEventCreateWithFlags(&evJoin, cudaEventDisableTiming);
    }

    const int nblk = (N_NODES + 255) / 256;
    const int eblk = (N_EDGES + 255) / 256;
    const int gemm_blocks = (N_NODES + 127) / 128;
    const int gath_blocks = (N_NODES * 8 + 255) / 256;

    // serial prefix: degrees + dinv (GEMM input scaling needs dinv)
    k_deg_init<<<nblk, 256>>>();
    k_deg_count<<<(N_EDGES / 4 + 255) / 256, 256>>>(ei);
    k_dinv<<<nblk, 256>>>();

    // fork: scan+fill on s2 || GEMM1 on main
    cudaEventRecord(evFork, 0);
    cudaStreamWaitEvent(s2, evFork, 0);

    k_scanA<<<NB_SCAN, 256, 0, s2>>>();
    k_scanB<<<1, 512, 0, s2>>>();
    k_scanC<<<nblk, 256, 0, s2>>>();
    k_fill<<<eblk, 256, 0, s2>>>(ei);

    k_gcn_gemm<false><<<gemm_blocks, 256>>>(x, W1, hs);   // concurrent

    cudaEventRecord(evJoin, s2);
    cudaStreamWaitEvent(0, evJoin, 0);

    // layer 1 aggregation
    k_gather<<<gath_blocks, 256>>>(hs, b1, agg);

    // layer 2
    k_gcn_gemm<true><<<gemm_blocks, 256>>>(agg, W2, hs);
    k_gather<<<gath_blocks, 256>>>(hs, b2, agg);

    // pool per graph + MLP head
    k_pool_head<<<N_GRAPHS, 64>>>(agg, bat, lw1, lb1, lw2, lb2, out);
}